// round 14
// baseline (speedup 1.0000x reference)
#include <cuda_runtime.h>
#include <cuda_fp16.h>
#include <math.h>
#include <stdint.h>

#define Bx 4
#define Nx 2048
#define Dx 1024
#define Hx 16
#define DHx 64
#define INNERx 1024
#define FFx 4096
#define ROWS (Bx*Nx)          // 8192

// ---------------- scratch ---------------------------------------------------
__device__ __half g_ln_h  [ROWS*Dx];
__device__ __half g_qkv_h [ROWS*3*INNERx];
__device__ __half g_att_h [ROWS*INNERx];
__device__ float  g_x1    [ROWS*Dx];
__device__ __half g_ff1_h [ROWS*FFx];
__device__ __half g_wqkv_h[Dx*3*INNERx];
__device__ __half g_wout_h[INNERx*Dx];
__device__ __half g_wff1_h[Dx*FFx];
__device__ __half g_wff2_h[FFx*Dx];
__device__ double g_hp    [4];

// ---------------- helpers ---------------------------------------------------
__device__ __forceinline__ uint32_t u32ptr(const void* p) {
    uint32_t a;
    asm("{ .reg .u64 t; cvta.to.shared.u64 t, %1; cvt.u32.u64 %0, t; }"
        : "=r"(a) : "l"(p));
    return a;
}
__device__ __forceinline__ float gelu_exact(float v) {
    return 0.5f * v * (1.0f + erff(v * 0.70710678118654752440f));
}
__device__ __forceinline__ uint32_t pk_h2(float a, float b) {
    __half2 h = __floats2half2_rn(a, b);
    return *(uint32_t*)&h;
}

#define CP_ASYNC16(dst, src) \
    asm volatile("cp.async.cg.shared.global [%0], [%1], 16;" :: "r"(dst), "l"(src))
#define CP_COMMIT() asm volatile("cp.async.commit_group;" ::: "memory")
#define CP_WAIT1()  asm volatile("cp.async.wait_group 1;" ::: "memory")
#define CP_WAIT0()  asm volatile("cp.async.wait_group 0;" ::: "memory")

__device__ __forceinline__ void ldsm_x4(uint32_t* r, uint32_t addr) {
    asm volatile("ldmatrix.sync.aligned.m8n8.x4.shared.b16 {%0,%1,%2,%3}, [%4];"
        : "=r"(r[0]), "=r"(r[1]), "=r"(r[2]), "=r"(r[3]) : "r"(addr));
}
__device__ __forceinline__ void ldsm_x4_t(uint32_t* r, uint32_t addr) {
    asm volatile("ldmatrix.sync.aligned.m8n8.x4.trans.shared.b16 {%0,%1,%2,%3}, [%4];"
        : "=r"(r[0]), "=r"(r[1]), "=r"(r[2]), "=r"(r[3]) : "r"(addr));
}
__device__ __forceinline__ void mma_f16(float* d, const uint32_t* a,
                                        const uint32_t* b) {
    asm volatile(
        "mma.sync.aligned.m16n8k16.row.col.f32.f16.f16.f32 "
        "{%0,%1,%2,%3}, {%4,%5,%6,%7}, {%8,%9}, {%0,%1,%2,%3};"
        : "+f"(d[0]), "+f"(d[1]), "+f"(d[2]), "+f"(d[3])
        : "r"(a[0]), "r"(a[1]), "r"(a[2]), "r"(a[3]), "r"(b[0]), "r"(b[1]));
}

// ---------------- LN row helper ---------------------------------------------
__device__ __forceinline__ void ln_row(const float* __restrict__ x,
                                       const float* __restrict__ g,
                                       const float* __restrict__ b,
                                       __half* __restrict__ y, int row, int tid)
{
    const float4* xr = (const float4*)(x + (size_t)row * Dx);
    float4 v = xr[tid];
    float s = v.x + v.y + v.z + v.w;
    float q = v.x*v.x + v.y*v.y + v.z*v.z + v.w*v.w;
    #pragma unroll
    for (int o = 16; o; o >>= 1) {
        s += __shfl_xor_sync(0xffffffffu, s, o);
        q += __shfl_xor_sync(0xffffffffu, q, o);
    }
    __shared__ float ss[8], qs[8];
    if ((tid & 31) == 0) { ss[tid >> 5] = s; qs[tid >> 5] = q; }
    __syncthreads();
    s = 0.f; q = 0.f;
    #pragma unroll
    for (int w = 0; w < 8; w++) { s += ss[w]; q += qs[w]; }
    float mean = s * (1.f / Dx);
    float var  = q * (1.f / Dx) - mean * mean;
    float inv  = rsqrtf(var + 1e-5f);
    float4 gv = ((const float4*)g)[tid];
    float4 bv = ((const float4*)b)[tid];
    __half2 h0 = __floats2half2_rn((v.x - mean) * inv * gv.x + bv.x,
                                   (v.y - mean) * inv * gv.y + bv.y);
    __half2 h1 = __floats2half2_rn((v.z - mean) * inv * gv.z + bv.z,
                                   (v.w - mean) * inv * gv.w + bv.w);
    *(uint2*)(y + (size_t)row * Dx + tid * 4) =
        make_uint2(*(uint32_t*)&h0, *(uint32_t*)&h1);
}

#define N_W0 (Dx*3*INNERx)
#define N_W1 (INNERx*Dx)
#define N_W2 (Dx*FFx)
#define N_W3 (FFx*Dx)
#define CB0 (N_W0/1024)
#define CB1 (N_W1/1024)
#define CB2 (N_W2/1024)
#define CB3 (N_W3/1024)

__global__ __launch_bounds__(256) void prep1_k(
    const float* __restrict__ x, const float* __restrict__ g,
    const float* __restrict__ b, __half* __restrict__ y,
    const float* __restrict__ W0, __half* __restrict__ W0h,
    double* __restrict__ hp)
{
    int blk = blockIdx.x, tid = threadIdx.x;
    if (blk == 0 && tid < 4) hp[tid] = 0.0;
    if (blk < ROWS) { ln_row(x, g, b, y, blk, tid); return; }
    int i = (blk - ROWS) * 1024 + tid * 4;
    float4 v = *(const float4*)(W0 + i);
    __half2 h0 = __floats2half2_rn(v.x, v.y);
    __half2 h1 = __floats2half2_rn(v.z, v.w);
    *(uint2*)(W0h + i) = make_uint2(*(uint32_t*)&h0, *(uint32_t*)&h1);
}

__global__ __launch_bounds__(256) void prep2_k(
    const float* __restrict__ W1, __half* __restrict__ W1h,
    const float* __restrict__ W2, __half* __restrict__ W2h,
    const float* __restrict__ W3, __half* __restrict__ W3h)
{
    int cid = blockIdx.x, tid = threadIdx.x;
    const float* W; __half* Wh;
    if (cid < CB1)            { W = W1; Wh = W1h; }
    else if (cid < CB1+CB2)   { W = W2; Wh = W2h; cid -= CB1; }
    else                      { W = W3; Wh = W3h; cid -= CB1+CB2; }
    int i = cid * 1024 + tid * 4;
    float4 v = *(const float4*)(W + i);
    __half2 h0 = __floats2half2_rn(v.x, v.y);
    __half2 h1 = __floats2half2_rn(v.z, v.w);
    *(uint2*)(Wh + i) = make_uint2(*(uint32_t*)&h0, *(uint32_t*)&h1);
}

__global__ __launch_bounds__(256) void ln_k(const float* __restrict__ x,
                                            const float* __restrict__ g,
                                            const float* __restrict__ b,
                                            __half* __restrict__ y)
{
    ln_row(x, g, b, y, blockIdx.x, threadIdx.x);
}

// ------- fp16 mma GEMM: 128x128 CTA, 256 threads, 3 stages, 2 CTAs/SM ------
#define SA 72
#define SBn 136
#define A_ST (128*SA)
#define B_ST (64*SBn)
#define STG  (A_ST + B_ST)
#define GEMM_SMEM (3*STG*2)                   // 107520 B -> 2 CTAs/SM

template<int EPI>
__global__ __launch_bounds__(256, 2) void hgemm(
    const __half* __restrict__ A, const __half* __restrict__ B,
    void* __restrict__ Cv, const float* __restrict__ bias,
    const float* __restrict__ res, const float* __restrict__ whalt,
    double* __restrict__ hp, int M, int N, int K)
{
    extern __shared__ __half hsm[];
    int tid = threadIdx.x, lane = tid & 31, warp = tid >> 5;
    int bm = blockIdx.y * 128, bn = blockIdx.x * 128;
    int wm = (warp & 1) * 64, wn = (warp >> 1) * 32;
    int g = lane >> 2, t4 = lane & 3;
    int lrow = lane & 15, lk = (lane >> 4) << 3;

    float acc[4][4][4];
    #pragma unroll
    for (int mi = 0; mi < 4; mi++)
        #pragma unroll
        for (int ni = 0; ni < 4; ni++)
            #pragma unroll
            for (int r = 0; r < 4; r++) acc[mi][ni][r] = 0.f;

    uint32_t sb = u32ptr(hsm);
    int arow = tid >> 3, ac8 = (tid & 7) * 8;
    int brow = tid >> 4, bc8 = (tid & 15) * 8;
    int nK = K >> 6;

    #pragma unroll
    for (int s = 0; s < 2; s++) {
        int kt = s * 64;
        #pragma unroll
        for (int it = 0; it < 4; it++) {
            int row = arow + it * 32;
            CP_ASYNC16(sb + (s*STG + row*SA + ac8)*2,
                       A + (size_t)(bm + row) * K + kt + ac8);
        }
        #pragma unroll
        for (int it = 0; it < 4; it++) {
            int row = brow + it * 16;
            CP_ASYNC16(sb + (s*STG + A_ST + row*SBn + bc8)*2,
                       B + (size_t)(kt + row) * N + bn + bc8);
        }
        CP_COMMIT();
    }

    int sl = 0;
    for (int i = 0; i < nK; i++) {
        if (i + 1 < nK) CP_WAIT1(); else CP_WAIT0();
        __syncthreads();

        int nx = i + 2;
        if (nx < nK) {
            int ns = sl + 2; if (ns >= 3) ns -= 3;
            int kt = nx * 64;
            #pragma unroll
            for (int it = 0; it < 4; it++) {
                int row = arow + it * 32;
                CP_ASYNC16(sb + (ns*STG + row*SA + ac8)*2,
                           A + (size_t)(bm + row) * K + kt + ac8);
            }
            #pragma unroll
            for (int it = 0; it < 4; it++) {
                int row = brow + it * 16;
                CP_ASYNC16(sb + (ns*STG + A_ST + row*SBn + bc8)*2,
                           B + (size_t)(kt + row) * N + bn + bc8);
            }
            CP_COMMIT();
        }

        uint32_t sA = sb + sl * STG * 2;
        uint32_t sB = sA + A_ST * 2;
        #pragma unroll
        for (int ks = 0; ks < 4; ks++) {
            int k = ks * 16;
            uint32_t af[4][4], bq[2][4];
            #pragma unroll
            for (int mi = 0; mi < 4; mi++)
                ldsm_x4(af[mi], sA + ((wm + 16*mi + lrow)*SA + k + lk)*2);
            #pragma unroll
            for (int p = 0; p < 2; p++)
                ldsm_x4_t(bq[p], sB + ((k + lrow)*SBn + wn + 16*p + lk)*2);
            #pragma unroll
            for (int mi = 0; mi < 4; mi++)
                #pragma unroll
                for (int p = 0; p < 2; p++) {
                    mma_f16(acc[mi][2*p],     af[mi], &bq[p][0]);
                    mma_f16(acc[mi][2*p + 1], af[mi], &bq[p][2]);
                }
        }
        if (++sl == 3) sl = 0;
    }

    float hpart = 0.f;
    #pragma unroll
    for (int mi = 0; mi < 4; mi++) {
        #pragma unroll
        for (int ni = 0; ni < 4; ni++) {
            int col = bn + wn + 8*ni + 2*t4;
            #pragma unroll
            for (int h = 0; h < 2; h++) {
                int row = bm + wm + 16*mi + g + 8*h;
                float v0 = acc[mi][ni][2*h + 0];
                float v1 = acc[mi][ni][2*h + 1];
                if (EPI == 0) {
                    *(__half2*)((__half*)Cv + (size_t)row * N + col) =
                        __floats2half2_rn(v0, v1);
                } else if (EPI == 1) {
                    v0 += bias[col]; v1 += bias[col + 1];
                    float2 rr = *(const float2*)(res + (size_t)row * N + col);
                    v0 += rr.x; v1 += rr.y;
                    *(float2*)((float*)Cv + (size_t)row * N + col) =
                        make_float2(v0, v1);
                    if (whalt) hpart += v0 * whalt[col] + v1 * whalt[col + 1];
                } else {
                    v0 = gelu_exact(v0 + bias[col]);
                    v1 = gelu_exact(v1 + bias[col + 1]);
                    *(__half2*)((__half*)Cv + (size_t)row * N + col) =
                        __floats2half2_rn(v0, v1);
                }
            }
        }
    }
    if (EPI == 1 && whalt) {
        __shared__ double hs[256];
        hs[tid] = (double)hpart;
        __syncthreads();
        for (int s = 128; s > 0; s >>= 1) {
            if (tid < s) hs[tid] += hs[tid + s];
            __syncthreads();
        }
        if (tid == 0) atomicAdd(hp + (bm >> 11), hs[0]);
    }
}

// ------ fp16 flash attention: 128-q tile, 8 warps, register P (FA2 style) --
#define FSA 72
#define FKV (64*FSA)
#define FLASH_SMEM ((4*FKV + 128*FSA)*2)     // 55296 B

__global__ __launch_bounds__(256) void flashh_k(const __half* __restrict__ qkv,
                                                __half* __restrict__ out)
{
    extern __shared__ __half fsm[];
    uint32_t sb = u32ptr(fsm);
    uint32_t sP = sb + 4 * FKV * 2;          // Q staging only

    int qt = (gridDim.x - 1) - blockIdx.x;
    int bh = blockIdx.y;
    int b = bh >> 4, h = bh & 15;
    int tid = threadIdx.x, lane = tid & 31, warp = tid >> 5;
    int g = lane >> 2, t4 = lane & 3;
    int lrow = lane & 15, lk = (lane >> 4) << 3;
    int brow = (lane & 7) + ((lane & 16) >> 1);
    int bk = lane & 8;
    const float scl2 = 0.125f * 1.4426950408889634f;

    size_t base = (size_t)b * Nx * 3072;
    const __half* Qg = qkv + base + (size_t)qt * 128 * 3072 + h * 64;
    int jmax = 2 * qt + 1;

    {
        #pragma unroll
        for (int it = 0; it < 4; it++) {
            int id = tid + it * 256;
            int rr = id >> 3, cc = (id & 7) * 8;
            CP_ASYNC16(sP + (rr*FSA + cc)*2, Qg + (size_t)rr * 3072 + cc);
        }
        CP_COMMIT();
        const __half* Kg = qkv + base + 1024 + h * 64;
        const __half* Vg = qkv + base + 2048 + h * 64;
        #pragma unroll
        for (int it = 0; it < 2; it++) {
            int id = tid + it * 256;
            int rr = id >> 3, cc = (id & 7) * 8;
            CP_ASYNC16(sb + (0*FKV + rr*FSA + cc)*2, Kg + (size_t)rr * 3072 + cc);
            CP_ASYNC16(sb + (2*FKV + rr*FSA + cc)*2, Vg + (size_t)rr * 3072 + cc);
        }
        CP_COMMIT();
        CP_WAIT1();
        __syncthreads();
    }

    uint32_t qa[4][4];
    #pragma unroll
    for (int kf = 0; kf < 4; kf++)
        ldsm_x4(qa[kf], sP + ((16*warp + lrow)*FSA + 16*kf + lk)*2);

    float l0 = 0.f, l1 = 0.f;
    float o[8][4];
    #pragma unroll
    for (int ni = 0; ni < 8; ni++)
        #pragma unroll
        for (int r = 0; r < 4; r++) o[ni][r] = 0.f;

    for (int j = 0; j <= jmax; j++) {
        __syncthreads();
        int cur = j & 1;
        if (j + 1 <= jmax) {
            int ns = (j + 1) & 1;
            const __half* Kg = qkv + base + (size_t)(j+1) * 64 * 3072 + 1024 + h * 64;
            const __half* Vg = qkv + base + (size_t)(j+1) * 64 * 3072 + 2048 + h * 64;
            #pragma unroll
            for (int it = 0; it < 2; it++) {
                int id = tid + it * 256;
                int rr = id >> 3, cc = (id & 7) * 8;
                CP_ASYNC16(sb + (ns*FKV + rr*FSA + cc)*2,     Kg + (size_t)rr * 3072 + cc);
                CP_ASYNC16(sb + ((2+ns)*FKV + rr*FSA + cc)*2, Vg + (size_t)rr * 3072 + cc);
            }
            CP_COMMIT();
            CP_WAIT1();
        } else {
            CP_WAIT0();
        }
        __syncthreads();

        if (j == jmax && warp < 4) continue;

        uint32_t sK = sb + cur * FKV * 2;
        uint32_t sV = sb + (2 + cur) * FKV * 2;

        // ---- S = Q K^T (f32-acc) ----
        float s[8][4];
        #pragma unroll
        for (int ni = 0; ni < 8; ni++)
            s[ni][0] = s[ni][1] = s[ni][2] = s[ni][3] = 0.f;
        #pragma unroll
        for (int kf = 0; kf < 4; kf++) {
            uint32_t bq[4][4];
            #pragma unroll
            for (int p = 0; p < 4; p++)
                ldsm_x4(bq[p], sK + ((16*p + brow)*FSA + 16*kf + bk)*2);
            #pragma unroll
            for (int p = 0; p < 4; p++) {
                mma_f16(s[2*p],     qa[kf], &bq[p][0]);
                mma_f16(s[2*p + 1], qa[kf], &bq[p][2]);
            }
        }

        // ---- p = exp2(s*scl2), causal mask, row-sum ----
        int row0 = 16*warp + g, row1 = row0 + 8;
        bool diag = (j >= 2 * qt);
        int qg0 = 128*qt + row0, qg1 = 128*qt + row1;
        float ps0 = 0.f, ps1 = 0.f;
        #pragma unroll
        for (int ni = 0; ni < 8; ni++) {
            int c0 = 64*j + 8*ni + 2*t4;
            bool k0r0 = diag && (c0     > qg0);
            bool k1r0 = diag && (c0 + 1 > qg0);
            bool k0r1 = diag && (c0     > qg1);
            bool k1r1 = diag && (c0 + 1 > qg1);
            s[ni][0] = k0r0 ? 0.f : exp2f(s[ni][0] * scl2);
            s[ni][1] = k1r0 ? 0.f : exp2f(s[ni][1] * scl2);
            s[ni][2] = k0r1 ? 0.f : exp2f(s[ni][2] * scl2);
            s[ni][3] = k1r1 ? 0.f : exp2f(s[ni][3] * scl2);
            ps0 += s[ni][0] + s[ni][1];
            ps1 += s[ni][2] + s[ni][3];
        }
        #pragma unroll
        for (int ofs = 1; ofs < 4; ofs <<= 1) {
            ps0 += __shfl_xor_sync(0xffffffffu, ps0, ofs);
            ps1 += __shfl_xor_sync(0xffffffffu, ps1, ofs);
        }
        l0 += ps0;
        l1 += ps1;

        // ---- O += P V : P packed straight into A-fragments (no smem) ----
        #pragma unroll
        for (int kf = 0; kf < 4; kf++) {
            uint32_t pa[4];
            pa[0] = pk_h2(s[2*kf    ][0], s[2*kf    ][1]);  // row g,   k 2t4
            pa[1] = pk_h2(s[2*kf    ][2], s[2*kf    ][3]);  // row g+8, k 2t4
            pa[2] = pk_h2(s[2*kf + 1][0], s[2*kf + 1][1]);  // row g,   k 2t4+8
            pa[3] = pk_h2(s[2*kf + 1][2], s[2*kf + 1][3]);  // row g+8, k 2t4+8
            uint32_t vq[4][4];
            #pragma unroll
            for (int p = 0; p < 4; p++)
                ldsm_x4_t(vq[p], sV + ((16*kf + lrow)*FSA + 16*p + lk)*2);
            #pragma unroll
            for (int p = 0; p < 4; p++) {
                mma_f16(o[2*p],     pa, &vq[p][0]);
                mma_f16(o[2*p + 1], pa, &vq[p][2]);
            }
        }
    }

    float inv0 = 1.f / l0, inv1 = 1.f / l1;
    int row0 = 16*warp + g;
    size_t gr0 = (size_t)(b * Nx + qt * 128 + row0) * INNERx + h * 64;
    size_t gr1 = gr0 + (size_t)8 * INNERx;
    #pragma unroll
    for (int ni = 0; ni < 8; ni++) {
        int c = 8*ni + 2*t4;
        *(__half2*)(out + gr0 + c) = __floats2half2_rn(o[ni][0]*inv0, o[ni][1]*inv0);
        *(__half2*)(out + gr1 + c) = __floats2half2_rn(o[ni][2]*inv1, o[ni][3]*inv1);
    }
}

// ---------------- halt finalize ---------------------------------------------
__global__ __launch_bounds__(32) void halt2_k(const double* __restrict__ hp,
                                              const float* __restrict__ b0,
                                              float* __restrict__ out)
{
    int t = threadIdx.x;
    if (t < 4) out[t] = (float)(hp[t] / (double)Nx) + b0[0];
}

// ---------------- launch ----------------------------------------------------
extern "C" void kernel_launch(void* const* d_in, const int* in_sizes, int n_in,
                              void* d_out, int out_size)
{
    const float* x     = (const float*)d_in[0];
    const float* ln1_g = (const float*)d_in[1];
    const float* ln1_b = (const float*)d_in[2];
    const float* w_qkv = (const float*)d_in[3];
    const float* w_out = (const float*)d_in[4];
    const float* b_out = (const float*)d_in[5];
    const float* ln2_g = (const float*)d_in[6];
    const float* ln2_b = (const float*)d_in[7];
    const float* w_ff1 = (const float*)d_in[8];
    const float* b_ff1 = (const float*)d_in[9];
    const float* w_ff2 = (const float*)d_in[10];
    const float* b_ff2 = (const float*)d_in[11];
    const float* w_hlt = (const float*)d_in[12];
    const float* b_hlt = (const float*)d_in[13];

    float* out_x = (float*)d_out;
    float* out_h = out_x + (size_t)Bx * Nx * Dx;

    void *p_ln, *p_qkv, *p_att, *p_x1, *p_ff1, *p_hp;
    void *p_wqkv, *p_wout, *p_wff1, *p_wff2;
    cudaGetSymbolAddress(&p_ln, g_ln_h);
    cudaGetSymbolAddress(&p_qkv, g_qkv_h);
    cudaGetSymbolAddress(&p_att, g_att_h);
    cudaGetSymbolAddress(&p_x1, g_x1);
    cudaGetSymbolAddress(&p_ff1, g_ff1_h);
    cudaGetSymbolAddress(&p_hp, g_hp);
    cudaGetSymbolAddress(&p_wqkv, g_wqkv_h);
    cudaGetSymbolAddress(&p_wout, g_wout_h);
    cudaGetSymbolAddress(&p_wff1, g_wff1_h);
    cudaGetSymbolAddress(&p_wff2, g_wff2_h);
    __half* ln  = (__half*)p_ln;
    __half* qkv = (__half*)p_qkv;
    __half* att = (__half*)p_att;
    float*  x1  = (float*)p_x1;
    __half* ff1 = (__half*)p_ff1;
    double* hp  = (double*)p_hp;

    static cudaStream_t s_aux = nullptr;
    static cudaEvent_t  e_fork = nullptr, e_join = nullptr;
    if (!s_aux) {
        cudaStreamCreateWithFlags(&s_aux, cudaStreamNonBlocking);
        cudaEventCreateWithFlags(&e_fork, cudaEventDisableTiming);
        cudaEventCreateWithFlags(&e_join, cudaEventDisableTiming);
    }

    cudaFuncSetAttribute(flashh_k, cudaFuncAttributeMaxDynamicSharedMemorySize, FLASH_SMEM);
    cudaFuncSetAttribute(hgemm<0>, cudaFuncAttributeMaxDynamicSharedMemorySize, GEMM_SMEM);
    cudaFuncSetAttribute(hgemm<1>, cudaFuncAttributeMaxDynamicSharedMemorySize, GEMM_SMEM);
    cudaFuncSetAttribute(hgemm<2>, cudaFuncAttributeMaxDynamicSharedMemorySize, GEMM_SMEM);

    cudaEventRecord(e_fork, 0);
    cudaStreamWaitEvent(s_aux, e_fork, 0);
    prep2_k<<<CB1 + CB2 + CB3, 256, 0, s_aux>>>(
        w_out, (__half*)p_wout, w_ff1, (__half*)p_wff1, w_ff2, (__half*)p_wff2);
    cudaEventRecord(e_join, s_aux);

    prep1_k<<<ROWS + CB0, 256>>>(x, ln1_g, ln1_b, ln, w_qkv, (__half*)p_wqkv, hp);
    hgemm<0><<<dim3(3*INNERx/128, ROWS/128), 256, GEMM_SMEM>>>(
        ln, (const __half*)p_wqkv, qkv, nullptr, nullptr, nullptr, nullptr,
        ROWS, 3*INNERx, Dx);
    flashh_k<<<dim3(Nx/128, Bx*Hx), 256, FLASH_SMEM>>>(qkv, att);

    cudaStreamWaitEvent(0, e_join, 0);

    hgemm<1><<<dim3(Dx/128, ROWS/128), 256, GEMM_SMEM>>>(
        att, (const __half*)p_wout, x1, b_out, x, nullptr, nullptr,
        ROWS, Dx, INNERx);
    ln_k<<<ROWS, 256>>>(x1, ln2_g, ln2_b, ln);
    hgemm<2><<<dim3(FFx/128, ROWS/128), 256, GEMM_SMEM>>>(
        ln, (const __half*)p_wff1, ff1, b_ff1, nullptr, nullptr, nullptr,
        ROWS, FFx, Dx);
    hgemm<1><<<dim3(Dx/128, ROWS/128), 256, GEMM_SMEM>>>(
        ff1, (const __half*)p_wff2, out_x, b_ff2, x1, w_hlt, hp,
        ROWS, Dx, FFx);
    halt2_k<<<1, 32>>>(hp, b_hlt, out_h);
}

// round 15
// speedup vs baseline: 1.5475x; 1.5475x over previous
#include <cuda_runtime.h>
#include <cuda_fp16.h>
#include <math.h>
#include <stdint.h>

#define Bx 4
#define Nx 2048
#define Dx 1024
#define Hx 16
#define DHx 64
#define INNERx 1024
#define FFx 4096
#define ROWS (Bx*Nx)          // 8192

// ---------------- scratch ---------------------------------------------------
__device__ __half g_ln_h  [ROWS*Dx];
__device__ __half g_qkv_h [ROWS*3*INNERx];
__device__ __half g_att_h [ROWS*INNERx];
__device__ float  g_x1    [ROWS*Dx];
__device__ __half g_ff1_h [ROWS*FFx];
__device__ __half g_wqkv_h[Dx*3*INNERx];
__device__ __half g_wout_h[INNERx*Dx];
__device__ __half g_wff1_h[Dx*FFx];
__device__ __half g_wff2_h[FFx*Dx];
__device__ double g_hp    [4];

// ---------------- helpers ---------------------------------------------------
__device__ __forceinline__ uint32_t u32ptr(const void* p) {
    uint32_t a;
    asm("{ .reg .u64 t; cvta.to.shared.u64 t, %1; cvt.u32.u64 %0, t; }"
        : "=r"(a) : "l"(p));
    return a;
}
__device__ __forceinline__ float gelu_exact(float v) {
    return 0.5f * v * (1.0f + erff(v * 0.70710678118654752440f));
}

#define CP_ASYNC16(dst, src) \
    asm volatile("cp.async.cg.shared.global [%0], [%1], 16;" :: "r"(dst), "l"(src))
#define CP_COMMIT() asm volatile("cp.async.commit_group;" ::: "memory")
#define CP_WAIT1()  asm volatile("cp.async.wait_group 1;" ::: "memory")
#define CP_WAIT0()  asm volatile("cp.async.wait_group 0;" ::: "memory")

__device__ __forceinline__ void ldsm_x4(uint32_t* r, uint32_t addr) {
    asm volatile("ldmatrix.sync.aligned.m8n8.x4.shared.b16 {%0,%1,%2,%3}, [%4];"
        : "=r"(r[0]), "=r"(r[1]), "=r"(r[2]), "=r"(r[3]) : "r"(addr));
}
__device__ __forceinline__ void ldsm_x4_t(uint32_t* r, uint32_t addr) {
    asm volatile("ldmatrix.sync.aligned.m8n8.x4.trans.shared.b16 {%0,%1,%2,%3}, [%4];"
        : "=r"(r[0]), "=r"(r[1]), "=r"(r[2]), "=r"(r[3]) : "r"(addr));
}
__device__ __forceinline__ void mma_f16(float* d, const uint32_t* a,
                                        const uint32_t* b) {
    asm volatile(
        "mma.sync.aligned.m16n8k16.row.col.f32.f16.f16.f32 "
        "{%0,%1,%2,%3}, {%4,%5,%6,%7}, {%8,%9}, {%0,%1,%2,%3};"
        : "+f"(d[0]), "+f"(d[1]), "+f"(d[2]), "+f"(d[3])
        : "r"(a[0]), "r"(a[1]), "r"(a[2]), "r"(a[3]), "r"(b[0]), "r"(b[1]));
}

// ---------------- LN row helper ---------------------------------------------
__device__ __forceinline__ void ln_row(const float* __restrict__ x,
                                       const float* __restrict__ g,
                                       const float* __restrict__ b,
                                       __half* __restrict__ y, int row, int tid)
{
    const float4* xr = (const float4*)(x + (size_t)row * Dx);
    float4 v = xr[tid];
    float s = v.x + v.y + v.z + v.w;
    float q = v.x*v.x + v.y*v.y + v.z*v.z + v.w*v.w;
    #pragma unroll
    for (int o = 16; o; o >>= 1) {
        s += __shfl_xor_sync(0xffffffffu, s, o);
        q += __shfl_xor_sync(0xffffffffu, q, o);
    }
    __shared__ float ss[8], qs[8];
    if ((tid & 31) == 0) { ss[tid >> 5] = s; qs[tid >> 5] = q; }
    __syncthreads();
    s = 0.f; q = 0.f;
    #pragma unroll
    for (int w = 0; w < 8; w++) { s += ss[w]; q += qs[w]; }
    float mean = s * (1.f / Dx);
    float var  = q * (1.f / Dx) - mean * mean;
    float inv  = rsqrtf(var + 1e-5f);
    float4 gv = ((const float4*)g)[tid];
    float4 bv = ((const float4*)b)[tid];
    __half2 h0 = __floats2half2_rn((v.x - mean) * inv * gv.x + bv.x,
                                   (v.y - mean) * inv * gv.y + bv.y);
    __half2 h1 = __floats2half2_rn((v.z - mean) * inv * gv.z + bv.z,
                                   (v.w - mean) * inv * gv.w + bv.w);
    *(uint2*)(y + (size_t)row * Dx + tid * 4) =
        make_uint2(*(uint32_t*)&h0, *(uint32_t*)&h1);
}

#define N_W0 (Dx*3*INNERx)
#define N_W1 (INNERx*Dx)
#define N_W2 (Dx*FFx)
#define N_W3 (FFx*Dx)
#define CB0 (N_W0/1024)
#define CB1 (N_W1/1024)
#define CB2 (N_W2/1024)
#define CB3 (N_W3/1024)

__global__ __launch_bounds__(256) void prep1_k(
    const float* __restrict__ x, const float* __restrict__ g,
    const float* __restrict__ b, __half* __restrict__ y,
    const float* __restrict__ W0, __half* __restrict__ W0h,
    double* __restrict__ hp)
{
    int blk = blockIdx.x, tid = threadIdx.x;
    if (blk == 0 && tid < 4) hp[tid] = 0.0;
    if (blk < ROWS) { ln_row(x, g, b, y, blk, tid); return; }
    int i = (blk - ROWS) * 1024 + tid * 4;
    float4 v = *(const float4*)(W0 + i);
    __half2 h0 = __floats2half2_rn(v.x, v.y);
    __half2 h1 = __floats2half2_rn(v.z, v.w);
    *(uint2*)(W0h + i) = make_uint2(*(uint32_t*)&h0, *(uint32_t*)&h1);
}

__global__ __launch_bounds__(256) void prep2_k(
    const float* __restrict__ W1, __half* __restrict__ W1h,
    const float* __restrict__ W2, __half* __restrict__ W2h,
    const float* __restrict__ W3, __half* __restrict__ W3h)
{
    int cid = blockIdx.x, tid = threadIdx.x;
    const float* W; __half* Wh;
    if (cid < CB1)            { W = W1; Wh = W1h; }
    else if (cid < CB1+CB2)   { W = W2; Wh = W2h; cid -= CB1; }
    else                      { W = W3; Wh = W3h; cid -= CB1+CB2; }
    int i = cid * 1024 + tid * 4;
    float4 v = *(const float4*)(W + i);
    __half2 h0 = __floats2half2_rn(v.x, v.y);
    __half2 h1 = __floats2half2_rn(v.z, v.w);
    *(uint2*)(Wh + i) = make_uint2(*(uint32_t*)&h0, *(uint32_t*)&h1);
}

__global__ __launch_bounds__(256) void ln_k(const float* __restrict__ x,
                                            const float* __restrict__ g,
                                            const float* __restrict__ b,
                                            __half* __restrict__ y)
{
    ln_row(x, g, b, y, blockIdx.x, threadIdx.x);
}

// ------- fp16 mma GEMM: 128x128 CTA, 256 threads, 3 stages, 2 CTAs/SM ------
#define SA 72
#define SBn 136
#define A_ST (128*SA)
#define B_ST (64*SBn)
#define STG  (A_ST + B_ST)
#define GEMM_SMEM (3*STG*2)                   // 107520 B -> 2 CTAs/SM

template<int EPI>
__global__ __launch_bounds__(256, 2) void hgemm(
    const __half* __restrict__ A, const __half* __restrict__ B,
    void* __restrict__ Cv, const float* __restrict__ bias,
    const float* __restrict__ res, const float* __restrict__ whalt,
    double* __restrict__ hp, int M, int N, int K)
{
    extern __shared__ __half hsm[];
    int tid = threadIdx.x, lane = tid & 31, warp = tid >> 5;
    int bm = blockIdx.y * 128, bn = blockIdx.x * 128;
    int wm = (warp & 1) * 64, wn = (warp >> 1) * 32;
    int g = lane >> 2, t4 = lane & 3;
    int lrow = lane & 15, lk = (lane >> 4) << 3;

    float acc[4][4][4];
    #pragma unroll
    for (int mi = 0; mi < 4; mi++)
        #pragma unroll
        for (int ni = 0; ni < 4; ni++)
            #pragma unroll
            for (int r = 0; r < 4; r++) acc[mi][ni][r] = 0.f;

    uint32_t sb = u32ptr(hsm);
    int arow = tid >> 3, ac8 = (tid & 7) * 8;
    int brow = tid >> 4, bc8 = (tid & 15) * 8;
    int nK = K >> 6;

    #pragma unroll
    for (int s = 0; s < 2; s++) {
        int kt = s * 64;
        #pragma unroll
        for (int it = 0; it < 4; it++) {
            int row = arow + it * 32;
            CP_ASYNC16(sb + (s*STG + row*SA + ac8)*2,
                       A + (size_t)(bm + row) * K + kt + ac8);
        }
        #pragma unroll
        for (int it = 0; it < 4; it++) {
            int row = brow + it * 16;
            CP_ASYNC16(sb + (s*STG + A_ST + row*SBn + bc8)*2,
                       B + (size_t)(kt + row) * N + bn + bc8);
        }
        CP_COMMIT();
    }

    int sl = 0;
    for (int i = 0; i < nK; i++) {
        if (i + 1 < nK) CP_WAIT1(); else CP_WAIT0();
        __syncthreads();

        int nx = i + 2;
        if (nx < nK) {
            int ns = sl + 2; if (ns >= 3) ns -= 3;
            int kt = nx * 64;
            #pragma unroll
            for (int it = 0; it < 4; it++) {
                int row = arow + it * 32;
                CP_ASYNC16(sb + (ns*STG + row*SA + ac8)*2,
                           A + (size_t)(bm + row) * K + kt + ac8);
            }
            #pragma unroll
            for (int it = 0; it < 4; it++) {
                int row = brow + it * 16;
                CP_ASYNC16(sb + (ns*STG + A_ST + row*SBn + bc8)*2,
                           B + (size_t)(kt + row) * N + bn + bc8);
            }
            CP_COMMIT();
        }

        uint32_t sA = sb + sl * STG * 2;
        uint32_t sB = sA + A_ST * 2;
        #pragma unroll
        for (int ks = 0; ks < 4; ks++) {
            int k = ks * 16;
            uint32_t af[4][4], bq[2][4];
            #pragma unroll
            for (int mi = 0; mi < 4; mi++)
                ldsm_x4(af[mi], sA + ((wm + 16*mi + lrow)*SA + k + lk)*2);
            #pragma unroll
            for (int p = 0; p < 2; p++)
                ldsm_x4_t(bq[p], sB + ((k + lrow)*SBn + wn + 16*p + lk)*2);
            #pragma unroll
            for (int mi = 0; mi < 4; mi++)
                #pragma unroll
                for (int p = 0; p < 2; p++) {
                    mma_f16(acc[mi][2*p],     af[mi], &bq[p][0]);
                    mma_f16(acc[mi][2*p + 1], af[mi], &bq[p][2]);
                }
        }
        if (++sl == 3) sl = 0;
    }

    float hpart = 0.f;
    #pragma unroll
    for (int mi = 0; mi < 4; mi++) {
        #pragma unroll
        for (int ni = 0; ni < 4; ni++) {
            int col = bn + wn + 8*ni + 2*t4;
            #pragma unroll
            for (int h = 0; h < 2; h++) {
                int row = bm + wm + 16*mi + g + 8*h;
                float v0 = acc[mi][ni][2*h + 0];
                float v1 = acc[mi][ni][2*h + 1];
                if (EPI == 0) {
                    *(__half2*)((__half*)Cv + (size_t)row * N + col) =
                        __floats2half2_rn(v0, v1);
                } else if (EPI == 1) {
                    v0 += bias[col]; v1 += bias[col + 1];
                    float2 rr = *(const float2*)(res + (size_t)row * N + col);
                    v0 += rr.x; v1 += rr.y;
                    *(float2*)((float*)Cv + (size_t)row * N + col) =
                        make_float2(v0, v1);
                    if (whalt) hpart += v0 * whalt[col] + v1 * whalt[col + 1];
                } else {
                    v0 = gelu_exact(v0 + bias[col]);
                    v1 = gelu_exact(v1 + bias[col + 1]);
                    *(__half2*)((__half*)Cv + (size_t)row * N + col) =
                        __floats2half2_rn(v0, v1);
                }
            }
        }
    }
    if (EPI == 1 && whalt) {
        __shared__ double hs[256];
        hs[tid] = (double)hpart;
        __syncthreads();
        for (int s = 128; s > 0; s >>= 1) {
            if (tid < s) hs[tid] += hs[tid + s];
            __syncthreads();
        }
        if (tid == 0) atomicAdd(hp + (bm >> 11), hs[0]);
    }
}

// ---------------- fp16 flash attention: 128-q tile, 8 warps, smem P --------
#define FSA 72
#define FKV (64*FSA)
#define FLASH_SMEM ((4*FKV + 128*FSA)*2)     // 55296 B

__global__ __launch_bounds__(256, 2) void flashh_k(const __half* __restrict__ qkv,
                                                   __half* __restrict__ out)
{
    extern __shared__ __half fsm[];
    __half* Ps = fsm + 4 * FKV;
    uint32_t sb = u32ptr(fsm);
    uint32_t sP = sb + 4 * FKV * 2;

    int qt = (gridDim.x - 1) - blockIdx.x;
    int bh = blockIdx.y;
    int b = bh >> 4, h = bh & 15;
    int tid = threadIdx.x, lane = tid & 31, warp = tid >> 5;
    int g = lane >> 2, t4 = lane & 3;
    int lrow = lane & 15, lk = (lane >> 4) << 3;
    int brow = (lane & 7) + ((lane & 16) >> 1);
    int bk = lane & 8;
    const float scl2 = 0.125f * 1.4426950408889634f;

    size_t base = (size_t)b * Nx * 3072;
    const __half* Qg = qkv + base + (size_t)qt * 128 * 3072 + h * 64;
    int jmax = 2 * qt + 1;

    {
        #pragma unroll
        for (int it = 0; it < 4; it++) {
            int id = tid + it * 256;
            int rr = id >> 3, cc = (id & 7) * 8;
            CP_ASYNC16(sP + (rr*FSA + cc)*2, Qg + (size_t)rr * 3072 + cc);
        }
        CP_COMMIT();
        const __half* Kg = qkv + base + 1024 + h * 64;
        const __half* Vg = qkv + base + 2048 + h * 64;
        #pragma unroll
        for (int it = 0; it < 2; it++) {
            int id = tid + it * 256;
            int rr = id >> 3, cc = (id & 7) * 8;
            CP_ASYNC16(sb + (0*FKV + rr*FSA + cc)*2, Kg + (size_t)rr * 3072 + cc);
            CP_ASYNC16(sb + (2*FKV + rr*FSA + cc)*2, Vg + (size_t)rr * 3072 + cc);
        }
        CP_COMMIT();
        CP_WAIT1();
        __syncthreads();
    }

    uint32_t qa[4][4];
    #pragma unroll
    for (int kf = 0; kf < 4; kf++)
        ldsm_x4(qa[kf], sP + ((16*warp + lrow)*FSA + 16*kf + lk)*2);

    float l0 = 0.f, l1 = 0.f;
    float o[8][4];
    #pragma unroll
    for (int ni = 0; ni < 8; ni++)
        #pragma unroll
        for (int r = 0; r < 4; r++) o[ni][r] = 0.f;

    for (int j = 0; j <= jmax; j++) {
        __syncthreads();
        int cur = j & 1;
        if (j + 1 <= jmax) {
            int ns = (j + 1) & 1;
            const __half* Kg = qkv + base + (size_t)(j+1) * 64 * 3072 + 1024 + h * 64;
            const __half* Vg = qkv + base + (size_t)(j+1) * 64 * 3072 + 2048 + h * 64;
            #pragma unroll
            for (int it = 0; it < 2; it++) {
                int id = tid + it * 256;
                int rr = id >> 3, cc = (id & 7) * 8;
                CP_ASYNC16(sb + (ns*FKV + rr*FSA + cc)*2,     Kg + (size_t)rr * 3072 + cc);
                CP_ASYNC16(sb + ((2+ns)*FKV + rr*FSA + cc)*2, Vg + (size_t)rr * 3072 + cc);
            }
            CP_COMMIT();
            CP_WAIT1();
        } else {
            CP_WAIT0();
        }
        __syncthreads();

        if (j == jmax && warp < 4) continue;

        uint32_t sK = sb + cur * FKV * 2;
        uint32_t sV = sb + (2 + cur) * FKV * 2;

        float s[8][4];
        #pragma unroll
        for (int ni = 0; ni < 8; ni++)
            s[ni][0] = s[ni][1] = s[ni][2] = s[ni][3] = 0.f;
        #pragma unroll
        for (int kf = 0; kf < 4; kf++) {
            uint32_t bq[4][4];
            #pragma unroll
            for (int p = 0; p < 4; p++)
                ldsm_x4(bq[p], sK + ((16*p + brow)*FSA + 16*kf + bk)*2);
            #pragma unroll
            for (int p = 0; p < 4; p++) {
                mma_f16(s[2*p],     qa[kf], &bq[p][0]);
                mma_f16(s[2*p + 1], qa[kf], &bq[p][2]);
            }
        }

        int row0 = 16*warp + g, row1 = row0 + 8;
        bool diag = (j >= 2 * qt);
        int qg0 = 128*qt + row0, qg1 = 128*qt + row1;
        float ps0 = 0.f, ps1 = 0.f;
        #pragma unroll
        for (int ni = 0; ni < 8; ni++) {
            int c0 = 64*j + 8*ni + 2*t4;
            bool k0r0 = diag && (c0     > qg0);
            bool k1r0 = diag && (c0 + 1 > qg0);
            bool k0r1 = diag && (c0     > qg1);
            bool k1r1 = diag && (c0 + 1 > qg1);
            s[ni][0] = k0r0 ? 0.f : exp2f(s[ni][0] * scl2);
            s[ni][1] = k1r0 ? 0.f : exp2f(s[ni][1] * scl2);
            s[ni][2] = k0r1 ? 0.f : exp2f(s[ni][2] * scl2);
            s[ni][3] = k1r1 ? 0.f : exp2f(s[ni][3] * scl2);
            ps0 += s[ni][0] + s[ni][1];
            ps1 += s[ni][2] + s[ni][3];
        }
        #pragma unroll
        for (int ofs = 1; ofs < 4; ofs <<= 1) {
            ps0 += __shfl_xor_sync(0xffffffffu, ps0, ofs);
            ps1 += __shfl_xor_sync(0xffffffffu, ps1, ofs);
        }
        l0 += ps0;
        l1 += ps1;

        #pragma unroll
        for (int ni = 0; ni < 8; ni++) {
            *(__half2*)(Ps + row0*FSA + 8*ni + 2*t4) = __floats2half2_rn(s[ni][0], s[ni][1]);
            *(__half2*)(Ps + row1*FSA + 8*ni + 2*t4) = __floats2half2_rn(s[ni][2], s[ni][3]);
        }
        __syncwarp();
        uint32_t pa[4][4];
        #pragma unroll
        for (int kf = 0; kf < 4; kf++)
            ldsm_x4(pa[kf], sP + ((16*warp + lrow)*FSA + 16*kf + lk)*2);
        #pragma unroll
        for (int kf = 0; kf < 4; kf++) {
            uint32_t vq[4][4];
            #pragma unroll
            for (int p = 0; p < 4; p++)
                ldsm_x4_t(vq[p], sV + ((16*kf + lrow)*FSA + 16*p + lk)*2);
            #pragma unroll
            for (int p = 0; p < 4; p++) {
                mma_f16(o[2*p],     pa[kf], &vq[p][0]);
                mma_f16(o[2*p + 1], pa[kf], &vq[p][2]);
            }
        }
    }

    float inv0 = 1.f / l0, inv1 = 1.f / l1;
    int row0 = 16*warp + g;
    size_t gr0 = (size_t)(b * Nx + qt * 128 + row0) * INNERx + h * 64;
    size_t gr1 = gr0 + (size_t)8 * INNERx;
    #pragma unroll
    for (int ni = 0; ni < 8; ni++) {
        int c = 8*ni + 2*t4;
        *(__half2*)(out + gr0 + c) = __floats2half2_rn(o[ni][0]*inv0, o[ni][1]*inv0);
        *(__half2*)(out + gr1 + c) = __floats2half2_rn(o[ni][2]*inv1, o[ni][3]*inv1);
    }
}

// ---------------- halt finalize ---------------------------------------------
__global__ __launch_bounds__(32) void halt2_k(const double* __restrict__ hp,
                                              const float* __restrict__ b0,
                                              float* __restrict__ out)
{
    int t = threadIdx.x;
    if (t < 4) out[t] = (float)(hp[t] / (double)Nx) + b0[0];
}

// ---------------- launch ----------------------------------------------------
extern "C" void kernel_launch(void* const* d_in, const int* in_sizes, int n_in,
                              void* d_out, int out_size)
{
    const float* x     = (const float*)d_in[0];
    const float* ln1_g = (const float*)d_in[1];
    const float* ln1_b = (const float*)d_in[2];
    const float* w_qkv = (const float*)d_in[3];
    const float* w_out = (const float*)d_in[4];
    const float* b_out = (const float*)d_in[5];
    const float* ln2_g = (const float*)d_in[6];
    const float* ln2_b = (const float*)d_in[7];
    const float* w_ff1 = (const float*)d_in[8];
    const float* b_ff1 = (const float*)d_in[9];
    const float* w_ff2 = (const float*)d_in[10];
    const float* b_ff2 = (const float*)d_in[11];
    const float* w_hlt = (const float*)d_in[12];
    const float* b_hlt = (const float*)d_in[13];

    float* out_x = (float*)d_out;
    float* out_h = out_x + (size_t)Bx * Nx * Dx;

    void *p_ln, *p_qkv, *p_att, *p_x1, *p_ff1, *p_hp;
    void *p_wqkv, *p_wout, *p_wff1, *p_wff2;
    cudaGetSymbolAddress(&p_ln, g_ln_h);
    cudaGetSymbolAddress(&p_qkv, g_qkv_h);
    cudaGetSymbolAddress(&p_att, g_att_h);
    cudaGetSymbolAddress(&p_x1, g_x1);
    cudaGetSymbolAddress(&p_ff1, g_ff1_h);
    cudaGetSymbolAddress(&p_hp, g_hp);
    cudaGetSymbolAddress(&p_wqkv, g_wqkv_h);
    cudaGetSymbolAddress(&p_wout, g_wout_h);
    cudaGetSymbolAddress(&p_wff1, g_wff1_h);
    cudaGetSymbolAddress(&p_wff2, g_wff2_h);
    __half* ln  = (__half*)p_ln;
    __half* qkv = (__half*)p_qkv;
    __half* att = (__half*)p_att;
    float*  x1  = (float*)p_x1;
    __half* ff1 = (__half*)p_ff1;
    double* hp  = (double*)p_hp;

    static cudaStream_t s_aux = nullptr;
    static cudaEvent_t  e_fork = nullptr, e_join = nullptr;
    if (!s_aux) {
        cudaStreamCreateWithFlags(&s_aux, cudaStreamNonBlocking);
        cudaEventCreateWithFlags(&e_fork, cudaEventDisableTiming);
        cudaEventCreateWithFlags(&e_join, cudaEventDisableTiming);
    }

    cudaFuncSetAttribute(flashh_k, cudaFuncAttributeMaxDynamicSharedMemorySize, FLASH_SMEM);
    cudaFuncSetAttribute(hgemm<0>, cudaFuncAttributeMaxDynamicSharedMemorySize, GEMM_SMEM);
    cudaFuncSetAttribute(hgemm<1>, cudaFuncAttributeMaxDynamicSharedMemorySize, GEMM_SMEM);
    cudaFuncSetAttribute(hgemm<2>, cudaFuncAttributeMaxDynamicSharedMemorySize, GEMM_SMEM);

    cudaEventRecord(e_fork, 0);
    cudaStreamWaitEvent(s_aux, e_fork, 0);
    prep2_k<<<CB1 + CB2 + CB3, 256, 0, s_aux>>>(
        w_out, (__half*)p_wout, w_ff1, (__half*)p_wff1, w_ff2, (__half*)p_wff2);
    cudaEventRecord(e_join, s_aux);

    prep1_k<<<ROWS + CB0, 256>>>(x, ln1_g, ln1_b, ln, w_qkv, (__half*)p_wqkv, hp);
    hgemm<0><<<dim3(3*INNERx/128, ROWS/128), 256, GEMM_SMEM>>>(
        ln, (const __half*)p_wqkv, qkv, nullptr, nullptr, nullptr, nullptr,
        ROWS, 3*INNERx, Dx);
    flashh_k<<<dim3(Nx/128, Bx*Hx), 256, FLASH_SMEM>>>(qkv, att);

    cudaStreamWaitEvent(0, e_join, 0);

    hgemm<1><<<dim3(Dx/128, ROWS/128), 256, GEMM_SMEM>>>(
        att, (const __half*)p_wout, x1, b_out, x, nullptr, nullptr,
        ROWS, Dx, INNERx);
    ln_k<<<ROWS, 256>>>(x1, ln2_g, ln2_b, ln);
    hgemm<2><<<dim3(FFx/128, ROWS/128), 256, GEMM_SMEM>>>(
        ln, (const __half*)p_wff1, ff1, b_ff1, nullptr, nullptr, nullptr,
        ROWS, FFx, Dx);
    hgemm<1><<<dim3(Dx/128, ROWS/128), 256, GEMM_SMEM>>>(
        ff1, (const __half*)p_wff2, out_x, b_ff2, x1, w_hlt, hp,
        ROWS, Dx, FFx);
    halt2_k<<<1, 32>>>(hp, b_hlt, out_h);
}

// round 17
// speedup vs baseline: 1.5621x; 1.0094x over previous
#include <cuda_runtime.h>
#include <cuda_fp16.h>
#include <math.h>
#include <stdint.h>

#define Bx 4
#define Nx 2048
#define Dx 1024
#define Hx 16
#define DHx 64
#define INNERx 1024
#define FFx 4096
#define ROWS (Bx*Nx)          // 8192

// ---------------- scratch ---------------------------------------------------
__device__ __half g_ln_h  [ROWS*Dx];
__device__ __half g_qkv_h [ROWS*3*INNERx];
__device__ __half g_att_h [ROWS*INNERx];
__device__ float  g_x1    [ROWS*Dx];
__device__ __half g_ff1_h [ROWS*FFx];
__device__ __half g_wqkv_h[Dx*3*INNERx];
__device__ __half g_wout_h[INNERx*Dx];
__device__ __half g_wff1_h[Dx*FFx];
__device__ __half g_wff2_h[FFx*Dx];
__device__ double g_hp    [4];

// ---------------- helpers ---------------------------------------------------
__device__ __forceinline__ uint32_t u32ptr(const void* p) {
    uint32_t a;
    asm("{ .reg .u64 t; cvta.to.shared.u64 t, %1; cvt.u32.u64 %0, t; }"
        : "=r"(a) : "l"(p));
    return a;
}
// fast tanh-form gelu: 0.5x(1+tanh(0.79788456(x+0.044715x^3)))
// tanh(y) = 1 - 2/(exp(2y)+1), exp via __expf (MUFU EX2)
__device__ __forceinline__ float gelu_fast(float x) {
    float x3 = x * x * x;
    float y  = 1.5957691216057308f * (x + 0.044715f * x3);  // 2*0.79788456*(...)
    float t  = 1.0f - 2.0f / (__expf(y) + 1.0f);            // tanh
    return 0.5f * x * (1.0f + t);
}

#define CP_ASYNC16(dst, src) \
    asm volatile("cp.async.cg.shared.global [%0], [%1], 16;" :: "r"(dst), "l"(src))
#define CP_COMMIT() asm volatile("cp.async.commit_group;" ::: "memory")
#define CP_WAIT1()  asm volatile("cp.async.wait_group 1;" ::: "memory")
#define CP_WAIT0()  asm volatile("cp.async.wait_group 0;" ::: "memory")

__device__ __forceinline__ void ldsm_x4(uint32_t* r, uint32_t addr) {
    asm volatile("ldmatrix.sync.aligned.m8n8.x4.shared.b16 {%0,%1,%2,%3}, [%4];"
        : "=r"(r[0]), "=r"(r[1]), "=r"(r[2]), "=r"(r[3]) : "r"(addr));
}
__device__ __forceinline__ void ldsm_x4_t(uint32_t* r, uint32_t addr) {
    asm volatile("ldmatrix.sync.aligned.m8n8.x4.trans.shared.b16 {%0,%1,%2,%3}, [%4];"
        : "=r"(r[0]), "=r"(r[1]), "=r"(r[2]), "=r"(r[3]) : "r"(addr));
}
__device__ __forceinline__ void mma_f16(float* d, const uint32_t* a,
                                        const uint32_t* b) {
    asm volatile(
        "mma.sync.aligned.m16n8k16.row.col.f32.f16.f16.f32 "
        "{%0,%1,%2,%3}, {%4,%5,%6,%7}, {%8,%9}, {%0,%1,%2,%3};"
        : "+f"(d[0]), "+f"(d[1]), "+f"(d[2]), "+f"(d[3])
        : "r"(a[0]), "r"(a[1]), "r"(a[2]), "r"(a[3]), "r"(b[0]), "r"(b[1]));
}

// ---------------- LN row helper ---------------------------------------------
__device__ __forceinline__ void ln_row(const float* __restrict__ x,
                                       const float* __restrict__ g,
                                       const float* __restrict__ b,
                                       __half* __restrict__ y, int row, int tid)
{
    const float4* xr = (const float4*)(x + (size_t)row * Dx);
    float4 v = xr[tid];
    float s = v.x + v.y + v.z + v.w;
    float q = v.x*v.x + v.y*v.y + v.z*v.z + v.w*v.w;
    #pragma unroll
    for (int o = 16; o; o >>= 1) {
        s += __shfl_xor_sync(0xffffffffu, s, o);
        q += __shfl_xor_sync(0xffffffffu, q, o);
    }
    __shared__ float ss[8], qs[8];
    if ((tid & 31) == 0) { ss[tid >> 5] = s; qs[tid >> 5] = q; }
    __syncthreads();
    s = 0.f; q = 0.f;
    #pragma unroll
    for (int w = 0; w < 8; w++) { s += ss[w]; q += qs[w]; }
    float mean = s * (1.f / Dx);
    float var  = q * (1.f / Dx) - mean * mean;
    float inv  = rsqrtf(var + 1e-5f);
    float4 gv = ((const float4*)g)[tid];
    float4 bv = ((const float4*)b)[tid];
    __half2 h0 = __floats2half2_rn((v.x - mean) * inv * gv.x + bv.x,
                                   (v.y - mean) * inv * gv.y + bv.y);
    __half2 h1 = __floats2half2_rn((v.z - mean) * inv * gv.z + bv.z,
                                   (v.w - mean) * inv * gv.w + bv.w);
    *(uint2*)(y + (size_t)row * Dx + tid * 4) =
        make_uint2(*(uint32_t*)&h0, *(uint32_t*)&h1);
}

#define N_W0 (Dx*3*INNERx)
#define N_W1 (INNERx*Dx)
#define N_W2 (Dx*FFx)
#define N_W3 (FFx*Dx)
#define CB0 (N_W0/1024)
#define CB1 (N_W1/1024)
#define CB2 (N_W2/1024)
#define CB3 (N_W3/1024)

__global__ __launch_bounds__(256) void prep1_k(
    const float* __restrict__ x, const float* __restrict__ g,
    const float* __restrict__ b, __half* __restrict__ y,
    const float* __restrict__ W0, __half* __restrict__ W0h,
    double* __restrict__ hp)
{
    int blk = blockIdx.x, tid = threadIdx.x;
    if (blk == 0 && tid < 4) hp[tid] = 0.0;
    if (blk < ROWS) { ln_row(x, g, b, y, blk, tid); return; }
    int i = (blk - ROWS) * 1024 + tid * 4;
    float4 v = *(const float4*)(W0 + i);
    __half2 h0 = __floats2half2_rn(v.x, v.y);
    __half2 h1 = __floats2half2_rn(v.z, v.w);
    *(uint2*)(W0h + i) = make_uint2(*(uint32_t*)&h0, *(uint32_t*)&h1);
}

__global__ __launch_bounds__(256) void prep2_k(
    const float* __restrict__ W1, __half* __restrict__ W1h,
    const float* __restrict__ W2, __half* __restrict__ W2h,
    const float* __restrict__ W3, __half* __restrict__ W3h)
{
    int cid = blockIdx.x, tid = threadIdx.x;
    const float* W; __half* Wh;
    if (cid < CB1)            { W = W1; Wh = W1h; }
    else if (cid < CB1+CB2)   { W = W2; Wh = W2h; cid -= CB1; }
    else                      { W = W3; Wh = W3h; cid -= CB1+CB2; }
    int i = cid * 1024 + tid * 4;
    float4 v = *(const float4*)(W + i);
    __half2 h0 = __floats2half2_rn(v.x, v.y);
    __half2 h1 = __floats2half2_rn(v.z, v.w);
    *(uint2*)(Wh + i) = make_uint2(*(uint32_t*)&h0, *(uint32_t*)&h1);
}

__global__ __launch_bounds__(256) void ln_k(const float* __restrict__ x,
                                            const float* __restrict__ g,
                                            const float* __restrict__ b,
                                            __half* __restrict__ y)
{
    ln_row(x, g, b, y, blockIdx.x, threadIdx.x);
}

// ------- fp16 mma GEMM: 128x128 CTA, 256 threads, 3 stages, 2 CTAs/SM ------
#define SA 72
#define SBn 136
#define A_ST (128*SA)
#define B_ST (64*SBn)
#define STG  (A_ST + B_ST)
#define GEMM_SMEM (3*STG*2)                   // 107520 B -> 2 CTAs/SM

template<int EPI>
__global__ __launch_bounds__(256, 2) void hgemm(
    const __half* __restrict__ A, const __half* __restrict__ B,
    void* __restrict__ Cv, const float* __restrict__ bias,
    const float* __restrict__ res, const float* __restrict__ whalt,
    double* __restrict__ hp, int M, int N, int K)
{
    extern __shared__ __half hsm[];
    int tid = threadIdx.x, lane = tid & 31, warp = tid >> 5;
    int bm = blockIdx.y * 128, bn = blockIdx.x * 128;
    int wm = (warp & 1) * 64, wn = (warp >> 1) * 32;
    int g = lane >> 2, t4 = lane & 3;
    int lrow = lane & 15, lk = (lane >> 4) << 3;

    float acc[4][4][4];
    #pragma unroll
    for (int mi = 0; mi < 4; mi++)
        #pragma unroll
        for (int ni = 0; ni < 4; ni++)
            #pragma unroll
            for (int r = 0; r < 4; r++) acc[mi][ni][r] = 0.f;

    uint32_t sb = u32ptr(hsm);
    int arow = tid >> 3, ac8 = (tid & 7) * 8;
    int brow = tid >> 4, bc8 = (tid & 15) * 8;
    int nK = K >> 6;

    #pragma unroll
    for (int s = 0; s < 2; s++) {
        int kt = s * 64;
        #pragma unroll
        for (int it = 0; it < 4; it++) {
            int row = arow + it * 32;
            CP_ASYNC16(sb + (s*STG + row*SA + ac8)*2,
                       A + (size_t)(bm + row) * K + kt + ac8);
        }
        #pragma unroll
        for (int it = 0; it < 4; it++) {
            int row = brow + it * 16;
            CP_ASYNC16(sb + (s*STG + A_ST + row*SBn + bc8)*2,
                       B + (size_t)(kt + row) * N + bn + bc8);
        }
        CP_COMMIT();
    }

    int sl = 0;
    for (int i = 0; i < nK; i++) {
        if (i + 1 < nK) CP_WAIT1(); else CP_WAIT0();
        __syncthreads();

        int nx = i + 2;
        if (nx < nK) {
            int ns = sl + 2; if (ns >= 3) ns -= 3;
            int kt = nx * 64;
            #pragma unroll
            for (int it = 0; it < 4; it++) {
                int row = arow + it * 32;
                CP_ASYNC16(sb + (ns*STG + row*SA + ac8)*2,
                           A + (size_t)(bm + row) * K + kt + ac8);
            }
            #pragma unroll
            for (int it = 0; it < 4; it++) {
                int row = brow + it * 16;
                CP_ASYNC16(sb + (ns*STG + A_ST + row*SBn + bc8)*2,
                           B + (size_t)(kt + row) * N + bn + bc8);
            }
            CP_COMMIT();
        }

        uint32_t sA = sb + sl * STG * 2;
        uint32_t sB = sA + A_ST * 2;
        #pragma unroll
        for (int ks = 0; ks < 4; ks++) {
            int k = ks * 16;
            uint32_t af[4][4], bq[2][4];
            #pragma unroll
            for (int mi = 0; mi < 4; mi++)
                ldsm_x4(af[mi], sA + ((wm + 16*mi + lrow)*SA + k + lk)*2);
            #pragma unroll
            for (int p = 0; p < 2; p++)
                ldsm_x4_t(bq[p], sB + ((k + lrow)*SBn + wn + 16*p + lk)*2);
            #pragma unroll
            for (int mi = 0; mi < 4; mi++)
                #pragma unroll
                for (int p = 0; p < 2; p++) {
                    mma_f16(acc[mi][2*p],     af[mi], &bq[p][0]);
                    mma_f16(acc[mi][2*p + 1], af[mi], &bq[p][2]);
                }
        }
        if (++sl == 3) sl = 0;
    }

    float hpart = 0.f;
    #pragma unroll
    for (int mi = 0; mi < 4; mi++) {
        #pragma unroll
        for (int ni = 0; ni < 4; ni++) {
            int col = bn + wn + 8*ni + 2*t4;
            #pragma unroll
            for (int h = 0; h < 2; h++) {
                int row = bm + wm + 16*mi + g + 8*h;
                float v0 = acc[mi][ni][2*h + 0];
                float v1 = acc[mi][ni][2*h + 1];
                if (EPI == 0) {
                    *(__half2*)((__half*)Cv + (size_t)row * N + col) =
                        __floats2half2_rn(v0, v1);
                } else if (EPI == 1) {
                    v0 += bias[col]; v1 += bias[col + 1];
                    float2 rr = *(const float2*)(res + (size_t)row * N + col);
                    v0 += rr.x; v1 += rr.y;
                    *(float2*)((float*)Cv + (size_t)row * N + col) =
                        make_float2(v0, v1);
                    if (whalt) hpart += v0 * whalt[col] + v1 * whalt[col + 1];
                } else {
                    v0 = gelu_fast(v0 + bias[col]);
                    v1 = gelu_fast(v1 + bias[col + 1]);
                    *(__half2*)((__half*)Cv + (size_t)row * N + col) =
                        __floats2half2_rn(v0, v1);
                }
            }
        }
    }
    if (EPI == 1 && whalt) {
        __shared__ double hs[256];
        hs[tid] = (double)hpart;
        __syncthreads();
        for (int s = 128; s > 0; s >>= 1) {
            if (tid < s) hs[tid] += hs[tid + s];
            __syncthreads();
        }
        if (tid == 0) atomicAdd(hp + (bm >> 11), hs[0]);
    }
}

// ---------------- fp16 flash attention: 128-q tile, 8 warps, smem P --------
#define FSA 72
#define FKV (64*FSA)
#define FLASH_SMEM ((4*FKV + 128*FSA)*2)     // 55296 B

__global__ __launch_bounds__(256, 2) void flashh_k(const __half* __restrict__ qkv,
                                                   __half* __restrict__ out)
{
    extern __shared__ __half fsm[];
    __half* Ps = fsm + 4 * FKV;
    uint32_t sb = u32ptr(fsm);
    uint32_t sP = sb + 4 * FKV * 2;

    int qt = (gridDim.x - 1) - blockIdx.x;
    int bh = blockIdx.y;
    int b = bh >> 4, h = bh & 15;
    int tid = threadIdx.x, lane = tid & 31, warp = tid >> 5;
    int g = lane >> 2, t4 = lane & 3;
    int lrow = lane & 15, lk = (lane >> 4) << 3;
    int brow = (lane & 7) + ((lane & 16) >> 1);
    int bk = lane & 8;
    const float scl2 = 0.125f * 1.4426950408889634f;

    size_t base = (size_t)b * Nx * 3072;
    const __half* Qg = qkv + base + (size_t)qt * 128 * 3072 + h * 64;
    int jmax = 2 * qt + 1;

    {
        #pragma unroll
        for (int it = 0; it < 4; it++) {
            int id = tid + it * 256;
            int rr = id >> 3, cc = (id & 7) * 8;
            CP_ASYNC16(sP + (rr*FSA + cc)*2, Qg + (size_t)rr * 3072 + cc);
        }
        CP_COMMIT();
        const __half* Kg = qkv + base + 1024 + h * 64;
        const __half* Vg = qkv + base + 2048 + h * 64;
        #pragma unroll
        for (int it = 0; it < 2; it++) {
            int id = tid + it * 256;
            int rr = id >> 3, cc = (id & 7) * 8;
            CP_ASYNC16(sb + (0*FKV + rr*FSA + cc)*2, Kg + (size_t)rr * 3072 + cc);
            CP_ASYNC16(sb + (2*FKV + rr*FSA + cc)*2, Vg + (size_t)rr * 3072 + cc);
        }
        CP_COMMIT();
        CP_WAIT1();
        __syncthreads();
    }

    uint32_t qa[4][4];
    #pragma unroll
    for (int kf = 0; kf < 4; kf++)
        ldsm_x4(qa[kf], sP + ((16*warp + lrow)*FSA + 16*kf + lk)*2);

    float l0 = 0.f, l1 = 0.f;
    float o[8][4];
    #pragma unroll
    for (int ni = 0; ni < 8; ni++)
        #pragma unroll
        for (int r = 0; r < 4; r++) o[ni][r] = 0.f;

    for (int j = 0; j <= jmax; j++) {
        __syncthreads();
        int cur = j & 1;
        if (j + 1 <= jmax) {
            int ns = (j + 1) & 1;
            const __half* Kg = qkv + base + (size_t)(j+1) * 64 * 3072 + 1024 + h * 64;
            const __half* Vg = qkv + base + (size_t)(j+1) * 64 * 3072 + 2048 + h * 64;
            #pragma unroll
            for (int it = 0; it < 2; it++) {
                int id = tid + it * 256;
                int rr = id >> 3, cc = (id & 7) * 8;
                CP_ASYNC16(sb + (ns*FKV + rr*FSA + cc)*2,     Kg + (size_t)rr * 3072 + cc);
                CP_ASYNC16(sb + ((2+ns)*FKV + rr*FSA + cc)*2, Vg + (size_t)rr * 3072 + cc);
            }
            CP_COMMIT();
            CP_WAIT1();
        } else {
            CP_WAIT0();
        }
        __syncthreads();

        if (j == jmax && warp < 4) continue;

        uint32_t sK = sb + cur * FKV * 2;
        uint32_t sV = sb + (2 + cur) * FKV * 2;

        float s[8][4];
        #pragma unroll
        for (int ni = 0; ni < 8; ni++)
            s[ni][0] = s[ni][1] = s[ni][2] = s[ni][3] = 0.f;
        #pragma unroll
        for (int kf = 0; kf < 4; kf++) {
            uint32_t bq[4][4];
            #pragma unroll
            for (int p = 0; p < 4; p++)
                ldsm_x4(bq[p], sK + ((16*p + brow)*FSA + 16*kf + bk)*2);
            #pragma unroll
            for (int p = 0; p < 4; p++) {
                mma_f16(s[2*p],     qa[kf], &bq[p][0]);
                mma_f16(s[2*p + 1], qa[kf], &bq[p][2]);
            }
        }

        int row0 = 16*warp + g, row1 = row0 + 8;
        bool diag = (j >= 2 * qt);
        int qg0 = 128*qt + row0, qg1 = 128*qt + row1;
        float ps0 = 0.f, ps1 = 0.f;
        #pragma unroll
        for (int ni = 0; ni < 8; ni++) {
            int c0 = 64*j + 8*ni + 2*t4;
            bool k0r0 = diag && (c0     > qg0);
            bool k1r0 = diag && (c0 + 1 > qg0);
            bool k0r1 = diag && (c0     > qg1);
            bool k1r1 = diag && (c0 + 1 > qg1);
            s[ni][0] = k0r0 ? 0.f : exp2f(s[ni][0] * scl2);
            s[ni][1] = k1r0 ? 0.f : exp2f(s[ni][1] * scl2);
            s[ni][2] = k0r1 ? 0.f : exp2f(s[ni][2] * scl2);
            s[ni][3] = k1r1 ? 0.f : exp2f(s[ni][3] * scl2);
            ps0 += s[ni][0] + s[ni][1];
            ps1 += s[ni][2] + s[ni][3];
        }
        #pragma unroll
        for (int ofs = 1; ofs < 4; ofs <<= 1) {
            ps0 += __shfl_xor_sync(0xffffffffu, ps0, ofs);
            ps1 += __shfl_xor_sync(0xffffffffu, ps1, ofs);
        }
        l0 += ps0;
        l1 += ps1;

        #pragma unroll
        for (int ni = 0; ni < 8; ni++) {
            *(__half2*)(Ps + row0*FSA + 8*ni + 2*t4) = __floats2half2_rn(s[ni][0], s[ni][1]);
            *(__half2*)(Ps + row1*FSA + 8*ni + 2*t4) = __floats2half2_rn(s[ni][2], s[ni][3]);
        }
        __syncwarp();
        uint32_t pa[4][4];
        #pragma unroll
        for (int kf = 0; kf < 4; kf++)
            ldsm_x4(pa[kf], sP + ((16*warp + lrow)*FSA + 16*kf + lk)*2);
        #pragma unroll
        for (int kf = 0; kf < 4; kf++) {
            uint32_t vq[4][4];
            #pragma unroll
            for (int p = 0; p < 4; p++)
                ldsm_x4_t(vq[p], sV + ((16*kf + lrow)*FSA + 16*p + lk)*2);
            #pragma unroll
            for (int p = 0; p < 4; p++) {
                mma_f16(o[2*p],     pa[kf], &vq[p][0]);
                mma_f16(o[2*p + 1], pa[kf], &vq[p][2]);
            }
        }
    }

    float inv0 = 1.f / l0, inv1 = 1.f / l1;
    int row0 = 16*warp + g;
    size_t gr0 = (size_t)(b * Nx + qt * 128 + row0) * INNERx + h * 64;
    size_t gr1 = gr0 + (size_t)8 * INNERx;
    #pragma unroll
    for (int ni = 0; ni < 8; ni++) {
        int c = 8*ni + 2*t4;
        *(__half2*)(out + gr0 + c) = __floats2half2_rn(o[ni][0]*inv0, o[ni][1]*inv0);
        *(__half2*)(out + gr1 + c) = __floats2half2_rn(o[ni][2]*inv1, o[ni][3]*inv1);
    }
}

// ---------------- halt finalize ---------------------------------------------
__global__ __launch_bounds__(32) void halt2_k(const double* __restrict__ hp,
                                              const float* __restrict__ b0,
                                              float* __restrict__ out)
{
    int t = threadIdx.x;
    if (t < 4) out[t] = (float)(hp[t] / (double)Nx) + b0[0];
}

// ---------------- launch ----------------------------------------------------
extern "C" void kernel_launch(void* const* d_in, const int* in_sizes, int n_in,
                              void* d_out, int out_size)
{
    const float* x     = (const float*)d_in[0];
    const float* ln1_g = (const float*)d_in[1];
    const float* ln1_b = (const float*)d_in[2];
    const float* w_qkv = (const float*)d_in[3];
    const float* w_out = (const float*)d_in[4];
    const float* b_out = (const float*)d_in[5];
    const float* ln2_g = (const float*)d_in[6];
    const float* ln2_b = (const float*)d_in[7];
    const float* w_ff1 = (const float*)d_in[8];
    const float* b_ff1 = (const float*)d_in[9];
    const float* w_ff2 = (const float*)d_in[10];
    const float* b_ff2 = (const float*)d_in[11];
    const float* w_hlt = (const float*)d_in[12];
    const float* b_hlt = (const float*)d_in[13];

    float* out_x = (float*)d_out;
    float* out_h = out_x + (size_t)Bx * Nx * Dx;

    void *p_ln, *p_qkv, *p_att, *p_x1, *p_ff1, *p_hp;
    void *p_wqkv, *p_wout, *p_wff1, *p_wff2;
    cudaGetSymbolAddress(&p_ln, g_ln_h);
    cudaGetSymbolAddress(&p_qkv, g_qkv_h);
    cudaGetSymbolAddress(&p_att, g_att_h);
    cudaGetSymbolAddress(&p_x1, g_x1);
    cudaGetSymbolAddress(&p_ff1, g_ff1_h);
    cudaGetSymbolAddress(&p_hp, g_hp);
    cudaGetSymbolAddress(&p_wqkv, g_wqkv_h);
    cudaGetSymbolAddress(&p_wout, g_wout_h);
    cudaGetSymbolAddress(&p_wff1, g_wff1_h);
    cudaGetSymbolAddress(&p_wff2, g_wff2_h);
    __half* ln  = (__half*)p_ln;
    __half* qkv = (__half*)p_qkv;
    __half* att = (__half*)p_att;
    float*  x1  = (float*)p_x1;
    __half* ff1 = (__half*)p_ff1;
    double* hp  = (double*)p_hp;

    static cudaStream_t s_aux = nullptr;
    static cudaEvent_t  e_fork = nullptr, e_join = nullptr;
    if (!s_aux) {
        cudaStreamCreateWithFlags(&s_aux, cudaStreamNonBlocking);
        cudaEventCreateWithFlags(&e_fork, cudaEventDisableTiming);
        cudaEventCreateWithFlags(&e_join, cudaEventDisableTiming);
    }

    cudaFuncSetAttribute(flashh_k, cudaFuncAttributeMaxDynamicSharedMemorySize, FLASH_SMEM);
    cudaFuncSetAttribute(hgemm<0>, cudaFuncAttributeMaxDynamicSharedMemorySize, GEMM_SMEM);
    cudaFuncSetAttribute(hgemm<1>, cudaFuncAttributeMaxDynamicSharedMemorySize, GEMM_SMEM);
    cudaFuncSetAttribute(hgemm<2>, cudaFuncAttributeMaxDynamicSharedMemorySize, GEMM_SMEM);

    cudaEventRecord(e_fork, 0);
    cudaStreamWaitEvent(s_aux, e_fork, 0);
    prep2_k<<<CB1 + CB2 + CB3, 256, 0, s_aux>>>(
        w_out, (__half*)p_wout, w_ff1, (__half*)p_wff1, w_ff2, (__half*)p_wff2);
    cudaEventRecord(e_join, s_aux);

    prep1_k<<<ROWS + CB0, 256>>>(x, ln1_g, ln1_b, ln, w_qkv, (__half*)p_wqkv, hp);
    hgemm<0><<<dim3(3*INNERx/128, ROWS/128), 256, GEMM_SMEM>>>(
        ln, (const __half*)p_wqkv, qkv, nullptr, nullptr, nullptr, nullptr,
        ROWS, 3*INNERx, Dx);
    flashh_k<<<dim3(Nx/128, Bx*Hx), 256, FLASH_SMEM>>>(qkv, att);

    cudaStreamWaitEvent(0, e_join, 0);

    hgemm<1><<<dim3(Dx/128, ROWS/128), 256, GEMM_SMEM>>>(
        att, (const __half*)p_wout, x1, b_out, x, nullptr, nullptr,
        ROWS, Dx, INNERx);
    ln_k<<<ROWS, 256>>>(x1, ln2_g, ln2_b, ln);
    hgemm<2><<<dim3(FFx/128, ROWS/128), 256, GEMM_SMEM>>>(
        ln, (const __half*)p_wff1, ff1, b_ff1, nullptr, nullptr, nullptr,
        ROWS, FFx, Dx);
    hgemm<1><<<dim3(Dx/128, ROWS/128), 256, GEMM_SMEM>>>(
        ff1, (const __half*)p_wff2, out_x, b_ff2, x1, w_hlt, hp,
        ROWS, Dx, FFx);
    halt2_k<<<1, 32>>>(hp, b_hlt, out_h);
}